// round 15
// baseline (speedup 1.0000x reference)
#include <cuda_runtime.h>
#include <cuda_bf16.h>
#include <cuda_fp16.h>
#include <math.h>
#include <stdint.h>

#define BB   8
#define LL   4096
#define BL   (BB*LL)
#define DD   512
#define CC   256
#define TT   2
#define HC   512
#define H2   1024
#define LN_EPS 1e-5f

// ---------------- fp32 scratch (ids for gsel; never passed from host) ------
__device__ float g_gb[BB*1024];          // 1
__device__ float g_gate[BB*DD];          // 2
__device__ float g_h[BB*HC];             // 3
__device__ float g_ctxadd[BB*DD];        // 4
__device__ float g_ctxtok[BB*TT*DD];     // 5
__device__ float g_m[32*DD];             // attention score vectors (b,t,h)
__device__ float g_vo[32*DD];            // out-projected v vectors (b,t,h)
__device__ float g_sb[32];               // per-(b,t,h) score bias
__device__ int   g_maskmode;

// ---------------- fp16 scratch (ids for hsel) -------------------------------
__device__ __half h_x   [(size_t)BL*DD];  // 1
__device__ __half h_ao  [(size_t)BL*DD];  // 7
__device__ __half h_p   [(size_t)BL*DD];  // 9
__device__ __half h_mh  [(size_t)BL*H2];  // 11
__device__ __half h_wc[DD*DD];            // 15
__device__ __half h_w1[H2*1536];          // 16
__device__ __half h_w2[DD*H2];            // 17
__device__ __half h_updc[(size_t)BL*DD];  // 18
__device__ __half h_upda[(size_t)BL*DD];  // 19

__device__ __forceinline__ float* gsel(const float* p, int id)
{
    switch (id) {
        case 1: return g_gb;     case 2: return g_gate;   case 3: return g_h;
        case 4: return g_ctxadd; case 5: return g_ctxtok;
        default: return const_cast<float*>(p);
    }
}
__device__ __forceinline__ __half* hsel(int id)
{
    switch (id) {
        case 1: return h_x;    case 7: return h_ao;   case 9: return h_p;
        case 11: return h_mh;  case 15: return h_wc;  case 16: return h_w1;
        case 17: return h_w2;  case 18: return h_updc;case 19: return h_upda;
        default: return nullptr;
    }
}

__device__ __forceinline__ uint32_t pack2h(__half a, __half b)
{
    return (uint32_t)__half_as_ushort(a) | ((uint32_t)__half_as_ushort(b) << 16);
}
__device__ __forceinline__ uint32_t smem_u32(const void* p)
{
    uint32_t a;
    asm("{ .reg .u64 t; cvta.to.shared.u64 t, %1; cvt.u32.u64 %0, t; }" : "=r"(a) : "l"(p));
    return a;
}
__device__ __forceinline__ void unpack2h(uint32_t w, float& a, float& b)
{
    a = __half2float(__ushort_as_half((unsigned short)(w & 0xffff)));
    b = __half2float(__ushort_as_half((unsigned short)(w >> 16)));
}

// ---------------- mask dtype detection -------------------------------------
__global__ void detect_mask_kernel(const unsigned char* __restrict__ m)
{
    __shared__ int s_gt1, s_odd;
    if (threadIdx.x == 0) { s_gt1 = 0; s_odd = 0; }
    __syncthreads();
    int lgt1 = 0, lodd = 0;
    for (int i = threadIdx.x; i < BL; i += 256) {
        unsigned char v = m[i];
        if (v > 1) lgt1 = 1;
        if ((i & 3) && v) lodd = 1;
    }
    if (lgt1) atomicOr(&s_gt1, 1);
    if (lodd) atomicOr(&s_odd, 1);
    __syncthreads();
    if (threadIdx.x == 0) g_maskmode = (!s_gt1 && s_odd) ? 1 : 0;
}

// ---------------- fused context stage-1 (warp per output, 4 sub-GEMMs) ------
// outputs: [0,8192) film->g_gb | [8192,12288) gate->g_gate |
//          [12288,16384) gelu ctx_w1->g_h | [16384,20480) ctxadd->g_ctxadd
__global__ void ctx_stage1(const float* __restrict__ context,
                           const float* __restrict__ film_w, const float* __restrict__ film_b,
                           const float* __restrict__ gate_w, const float* __restrict__ gate_b,
                           const float* __restrict__ ctx_w1, const float* __restrict__ ctx_b1,
                           const float* __restrict__ concat_w, const float* __restrict__ concat_b)
{
    int o = blockIdx.x * 8 + (threadIdx.x >> 5);
    if (o >= 20480) return;
    int lane = threadIdx.x & 31;
    int m, n, act; const float* w; const float* bias; float* outp; int oidx;
    if (o < 8192)       { int oo = o;         m = oo >> 10; n = oo & 1023; w = film_w + (size_t)n*CC; bias = film_b; act = 0; outp = g_gb;     oidx = oo; }
    else if (o < 12288) { int oo = o - 8192;  m = oo >> 9;  n = oo & 511;  w = gate_w + (size_t)n*CC; bias = gate_b; act = 2; outp = g_gate;   oidx = oo; }
    else if (o < 16384) { int oo = o - 12288; m = oo >> 9;  n = oo & 511;  w = ctx_w1 + (size_t)n*CC; bias = ctx_b1; act = 1; outp = g_h;      oidx = oo; }
    else                { int oo = o - 16384; m = oo >> 9;  n = oo & 511;  w = concat_w + (size_t)n*(DD+CC) + DD; bias = concat_b; act = 0; outp = g_ctxadd; oidx = oo; }
    const float* a = context + (size_t)m * CC;
    float s = 0.f;
    for (int k = lane; k < CC; k += 32) s += a[k] * w[k];
    #pragma unroll
    for (int off = 16; off; off >>= 1) s += __shfl_down_sync(0xffffffffu, s, off);
    if (lane == 0) {
        s += bias[n];
        if (act == 1)      s = 0.5f * s * (1.f + erff(s * 0.70710678118654752f));
        else if (act == 2) s = 1.f / (1.f + expf(-s));
        outp[oidx] = s;
    }
}

// ---------------- ctxtok (warp per output) ----------------------------------
__global__ void small_gemmW(const float* __restrict__ Ap, int Aid, int lda,
                            const float* __restrict__ W, int ldw,
                            const float* __restrict__ bias,
                            int outid, int M, int N, int K, int act)
{
    const float* A = gsel(Ap, Aid);
    float* out = gsel(nullptr, outid);
    int o = blockIdx.x * 8 + (threadIdx.x >> 5);
    if (o >= M * N) return;
    int lane = threadIdx.x & 31;
    int m = o / N, n = o % N;
    const float* a = A + (size_t)m * lda;
    const float* w = W + (size_t)n * ldw;
    float s = 0.f;
    for (int k = lane; k < K; k += 32) s += a[k] * w[k];
    #pragma unroll
    for (int off = 16; off; off >>= 1) s += __shfl_down_sync(0xffffffffu, s, off);
    if (lane == 0) {
        s += bias[n];
        if (act == 1)      s = 0.5f * s * (1.f + erff(s * 0.70710678118654752f));
        else if (act == 2) s = 1.f / (1.f + expf(-s));
        out[o] = s;
    }
}

// ---------------- fused k/v/m/vo/sb: one block per (b,t) --------------------
__global__ void kv_mvo_kernel(const float* __restrict__ in_proj_w,
                              const float* __restrict__ in_proj_b,
                              const float* __restrict__ out_proj_w,
                              const float* __restrict__ bq)
{
    int blk = blockIdx.x;          // 0..15
    int b = blk >> 1, t = blk & 1;
    int tid = threadIdx.x;         // 0..511
    __shared__ float sct[512], sk[512], sv[512];
    __shared__ float sred[16];

    sct[tid] = g_ctxtok[(size_t)(b*2 + t) * 512 + tid];
    __syncthreads();

    // k and v rows
    {
        const float* wk = in_proj_w + (size_t)(512 + tid) * 512;
        const float* wv = in_proj_w + (size_t)(1024 + tid) * 512;
        float a1 = 0.f, a2 = 0.f;
        #pragma unroll 4
        for (int j = 0; j < 512; j++) { float c = sct[j]; a1 += wk[j]*c; a2 += wv[j]*c; }
        sk[tid] = a1 + in_proj_b[512 + tid];
        sv[tid] = a2 + in_proj_b[1024 + tid];
    }
    __syncthreads();

    // m vectors: m[b*4+t*2+h][d] = sum_j wq[(h*256+j)*512+d] * sk[h*256+j]
    {
        int d = tid;
        float m0 = 0.f, m1 = 0.f;
        #pragma unroll 4
        for (int j = 0; j < 256; j++) {
            m0 += in_proj_w[(size_t)j * 512 + d] * sk[j];
            m1 += in_proj_w[(size_t)(256 + j) * 512 + d] * sk[256 + j];
        }
        g_m[(size_t)(b*4 + t*2 + 0)*512 + d] = m0;
        g_m[(size_t)(b*4 + t*2 + 1)*512 + d] = m1;
    }
    // vo vectors: vo[idx][d] = sum_j wo[d*512 + h*256 + j] * sv[h*256+j]
    {
        int d = tid;
        const float* wrow = out_proj_w + (size_t)d * 512;
        float o0 = 0.f, o1 = 0.f;
        #pragma unroll 4
        for (int j = 0; j < 256; j++) {
            o0 += wrow[j] * sv[j];
            o1 += wrow[256 + j] * sv[256 + j];
        }
        g_vo[(size_t)(b*4 + t*2 + 0)*512 + d] = o0;
        g_vo[(size_t)(b*4 + t*2 + 1)*512 + d] = o1;
    }
    // score biases: sb[idx] = dot(bq[h*256:+256], sk[h*256:+256])
    {
        int h = tid >> 8, j = tid & 255;
        float pb = bq[h*256 + j] * sk[h*256 + j];
        #pragma unroll
        for (int off = 16; off; off >>= 1) pb += __shfl_down_sync(0xffffffffu, pb, off);
        if ((tid & 31) == 0) sred[tid >> 5] = pb;
        __syncthreads();
        if (tid == 0) {
            float t0 = 0.f, t1 = 0.f;
            #pragma unroll
            for (int i = 0; i < 8; i++) { t0 += sred[i]; t1 += sred[8 + i]; }
            g_sb[b*4 + t*2 + 0] = t0;
            g_sb[b*4 + t*2 + 1] = t1;
        }
    }
}

// ---------------- fused weight prep (wc, w2, w1c -> fp16) -------------------
#define PW_WC  (DD*DD)            // 262144
#define PW_W2  (DD*H2)            // 524288
#define PW_TOT (PW_WC + PW_W2 + H2*1536)
__global__ void prep_weights(const float* __restrict__ concat_w,
                             const float* __restrict__ mix_w2,
                             const float* __restrict__ mw1)
{
    int i = blockIdx.x * blockDim.x + threadIdx.x;
    if (i >= PW_TOT) return;
    if (i < PW_WC) {
        int n = i >> 9, k = i & 511;
        h_wc[i] = __float2half_rn(concat_w[(size_t)n * (DD+CC) + k]);
    } else if (i < PW_WC + PW_W2) {
        int j = i - PW_WC;
        h_w2[j] = __float2half_rn(mix_w2[j]);
    } else {
        int j = i - PW_WC - PW_W2;
        int n = j / 1536, k = j % 1536;
        const float* r = mw1 + (size_t)n * 2048;
        float v;
        if      (k < 512)  v = r[k] + r[k + 1024];
        else if (k < 1024) v = r[k] - r[k + 512];
        else               v = r[k + 512];
        h_w1[j] = __float2half_rn(v);
    }
}

// ---------------- block reduce ----------------------------------------------
__device__ __forceinline__ float2 block_reduce2_128(float a, float b)
{
    __shared__ float sa[4], sb[4];
    __syncthreads();
    int lane = threadIdx.x & 31, w = threadIdx.x >> 5;
    #pragma unroll
    for (int o = 16; o; o >>= 1) {
        a += __shfl_down_sync(0xffffffffu, a, o);
        b += __shfl_down_sync(0xffffffffu, b, o);
    }
    if (lane == 0) { sa[w] = a; sb[w] = b; }
    __syncthreads();
    return make_float2(sa[0]+sa[1]+sa[2]+sa[3], sb[0]+sb[1]+sb[2]+sb[3]);
}

// ---------------- fused LN + attention + mix prep (vectorized) --------------
__global__ void ln_base_attn_kernel(const float* __restrict__ x,
                                    const float* __restrict__ qg, const float* __restrict__ qb,
                                    const float* __restrict__ bo)
{
    int row = blockIdx.x;
    int b = row >> 12;
    int tid = threadIdx.x;       // 128 threads, d0 = tid*4
    int d0 = tid * 4;
    const float4 xv = *reinterpret_cast<const float4*>(x + (size_t)row * DD + d0);
    float v[4] = {xv.x, xv.y, xv.z, xv.w};
    float s = v[0]+v[1]+v[2]+v[3];
    float s2 = v[0]*v[0]+v[1]*v[1]+v[2]*v[2]+v[3]*v[3];
    float2 r = block_reduce2_128(s, s2);
    float mean = r.x * (1.f / DD);
    float inv  = rsqrtf(r.y * (1.f / DD) - mean * mean + LN_EPS);

    // h_x (fp16 x)
    size_t vecidx = (size_t)row * 128 + tid;
    reinterpret_cast<uint2*>(h_x)[vecidx] = make_uint2(
        pack2h(__float2half_rn(v[0]), __float2half_rn(v[1])),
        pack2h(__float2half_rn(v[2]), __float2half_rn(v[3])));

    float4 qgv = *reinterpret_cast<const float4*>(qg + d0);
    float4 qbv = *reinterpret_cast<const float4*>(qb + d0);
    float xq[4];
    xq[0] = (v[0]-mean)*inv*qgv.x + qbv.x;
    xq[1] = (v[1]-mean)*inv*qgv.y + qbv.y;
    xq[2] = (v[2]-mean)*inv*qgv.z + qbv.z;
    xq[3] = (v[3]-mean)*inv*qgv.w + qbv.w;

    // 4 score dot products
    float sc[4];
    #pragma unroll
    for (int j = 0; j < 4; j++) {
        float4 mv = *reinterpret_cast<const float4*>(g_m + (size_t)(b*4 + j)*512 + d0);
        sc[j] = xq[0]*mv.x + xq[1]*mv.y + xq[2]*mv.z + xq[3]*mv.w;
    }
    __shared__ float red[4][4];
    int lane = tid & 31, w = tid >> 5;
    #pragma unroll
    for (int o = 16; o; o >>= 1) {
        sc[0] += __shfl_down_sync(0xffffffffu, sc[0], o);
        sc[1] += __shfl_down_sync(0xffffffffu, sc[1], o);
        sc[2] += __shfl_down_sync(0xffffffffu, sc[2], o);
        sc[3] += __shfl_down_sync(0xffffffffu, sc[3], o);
    }
    __syncthreads();
    if (lane == 0) { red[w][0]=sc[0]; red[w][1]=sc[1]; red[w][2]=sc[2]; red[w][3]=sc[3]; }
    __syncthreads();
    float s00 = (red[0][0]+red[1][0]+red[2][0]+red[3][0] + g_sb[b*4+0]) * 0.0625f; // t0 h0
    float s01 = (red[0][1]+red[1][1]+red[2][1]+red[3][1] + g_sb[b*4+1]) * 0.0625f; // t0 h1
    float s10 = (red[0][2]+red[1][2]+red[2][2]+red[3][2] + g_sb[b*4+2]) * 0.0625f; // t1 h0
    float s11 = (red[0][3]+red[1][3]+red[2][3]+red[3][3] + g_sb[b*4+3]) * 0.0625f; // t1 h1

    float m0 = fmaxf(s00, s10), m1 = fmaxf(s01, s11);
    float e00 = expf(s00 - m0), e10 = expf(s10 - m0);
    float e01 = expf(s01 - m1), e11 = expf(s11 - m1);
    float p00 = e00/(e00+e10), p01 = e10/(e00+e10);  // head0 weights (t0,t1)
    float p10 = e01/(e01+e11), p11 = e11/(e01+e11);  // head1 weights (t0,t1)

    float4 vo0 = *reinterpret_cast<const float4*>(g_vo + (size_t)(b*4 + 0)*512 + d0);
    float4 vo1 = *reinterpret_cast<const float4*>(g_vo + (size_t)(b*4 + 1)*512 + d0);
    float4 vo2 = *reinterpret_cast<const float4*>(g_vo + (size_t)(b*4 + 2)*512 + d0);
    float4 vo3 = *reinterpret_cast<const float4*>(g_vo + (size_t)(b*4 + 3)*512 + d0);
    float4 bov = *reinterpret_cast<const float4*>(bo + d0);
    float ao[4];
    ao[0] = p00*vo0.x + p10*vo1.x + p01*vo2.x + p11*vo3.x + bov.x;
    ao[1] = p00*vo0.y + p10*vo1.y + p01*vo2.y + p11*vo3.y + bov.y;
    ao[2] = p00*vo0.z + p10*vo1.z + p01*vo2.z + p11*vo3.z + bov.z;
    ao[3] = p00*vo0.w + p10*vo1.w + p01*vo2.w + p11*vo3.w + bov.w;

    reinterpret_cast<uint2*>(h_ao)[vecidx] = make_uint2(
        pack2h(__float2half_rn(ao[0]), __float2half_rn(ao[1])),
        pack2h(__float2half_rn(ao[2]), __float2half_rn(ao[3])));
    reinterpret_cast<uint2*>(h_p)[vecidx] = make_uint2(
        pack2h(__float2half_rn(v[0]*ao[0]), __float2half_rn(v[1]*ao[1])),
        pack2h(__float2half_rn(v[2]*ao[2]), __float2half_rn(v[3]*ao[3])));
}

// ---------------- final: recompute film base, concat-LN inline, out-LN ------
__global__ void final_kernel(const float* __restrict__ x,
                             const void* __restrict__ mask,
                             const float* __restrict__ fg, const float* __restrict__ fb,
                             const float* __restrict__ cg, const float* __restrict__ cb,
                             const float* __restrict__ og, const float* __restrict__ ob,
                             float* __restrict__ out)
{
    int row = blockIdx.x;
    int b = row >> 12;
    int tid = threadIdx.x;
    int d0 = tid * 4;
    float mk = (g_maskmode == 1) ? (((const unsigned char*)mask)[row] ? 1.f : 0.f)
                                 : ((((const int*)mask)[row] != 0) ? 1.f : 0.f);
    size_t vecidx = (size_t)row * 128 + tid;

    // x LN stats
    const float4 xv = *reinterpret_cast<const float4*>(x + (size_t)row * DD + d0);
    float v[4] = {xv.x, xv.y, xv.z, xv.w};
    float2 xr = block_reduce2_128(v[0]+v[1]+v[2]+v[3],
                                  v[0]*v[0]+v[1]*v[1]+v[2]*v[2]+v[3]*v[3]);
    float xmean = xr.x * (1.f / DD);
    float xinv  = rsqrtf(xr.y * (1.f / DD) - xmean * xmean + LN_EPS);

    // updc stats
    uint2 uw = reinterpret_cast<const uint2*>(h_updc)[vecidx];
    float u[4];
    unpack2h(uw.x, u[0], u[1]);
    unpack2h(uw.y, u[2], u[3]);
    float2 ur = block_reduce2_128(u[0]+u[1]+u[2]+u[3],
                                  u[0]*u[0]+u[1]*u[1]+u[2]*u[2]+u[3]*u[3]);
    float umean = ur.x * (1.f / DD);
    float uinv  = rsqrtf(ur.y * (1.f / DD) - umean * umean + LN_EPS);

    uint2 aw = reinterpret_cast<const uint2*>(h_upda)[vecidx];
    float ua[4];
    unpack2h(aw.x, ua[0], ua[1]);
    unpack2h(aw.y, ua[2], ua[3]);

    float4 fgv = *reinterpret_cast<const float4*>(fg + d0);
    float4 fbv = *reinterpret_cast<const float4*>(fb + d0);
    float4 gav = *reinterpret_cast<const float4*>(g_gb + b*1024 + d0);
    float4 bev = *reinterpret_cast<const float4*>(g_gb + b*1024 + 512 + d0);
    float4 cgv = *reinterpret_cast<const float4*>(cg + d0);
    float4 cbv = *reinterpret_cast<const float4*>(cb + d0);
    float4 gtv = *reinterpret_cast<const float4*>(g_gate + b*DD + d0);

    float fgA[4] = {fgv.x,fgv.y,fgv.z,fgv.w}, fbA[4] = {fbv.x,fbv.y,fbv.z,fbv.w};
    float gaA[4] = {gav.x,gav.y,gav.z,gav.w}, beA[4] = {bev.x,bev.y,bev.z,bev.w};
    float cgA[4] = {cgv.x,cgv.y,cgv.z,cgv.w}, cbA[4] = {cbv.x,cbv.y,cbv.z,cbv.w};
    float gtA[4] = {gtv.x,gtv.y,gtv.z,gtv.w};

    float val[4], vs = 0.f, vs2 = 0.f;
    #pragma unroll
    for (int i = 0; i < 4; i++) {
        float xh = (v[i] - xmean) * xinv;
        float base = (1.f + gaA[i]) * (xh * fgA[i] + fbA[i]) + beA[i];
        float uln  = (u[i] - umean) * uinv * cgA[i] + cbA[i];
        val[i] = base + gtA[i] * mk * (uln + ua[i]);
        vs += val[i]; vs2 += val[i] * val[i];
    }
    float2 rr = block_reduce2_128(vs, vs2);
    float mean = rr.x * (1.f / DD);
    float inv  = rsqrtf(rr.y * (1.f / DD) - mean * mean + LN_EPS);
    float4 ogv = *reinterpret_cast<const float4*>(og + d0);
    float4 obv = *reinterpret_cast<const float4*>(ob + d0);
    float4 o;
    o.x = (val[0] - mean) * inv * ogv.x + obv.x;
    o.y = (val[1] - mean) * inv * ogv.y + obv.y;
    o.z = (val[2] - mean) * inv * ogv.z + obv.z;
    o.w = (val[3] - mean) * inv * ogv.w + obv.w;
    *reinterpret_cast<float4*>(out + (size_t)row * DD + d0) = o;
}

// ---------------- mma.sync single-pass fp16 GEMM (ldmatrix fragments) --------
#define TSTRIDE 20
#define TILE_U32 (128*TSTRIDE)
#define TILE_B   (TILE_U32*4)
#define GM_SMEM  (4*TILE_B)

__device__ __forceinline__ void cpa16(uint32_t dst, const void* src)
{
    asm volatile("cp.async.cg.shared.global [%0], [%1], 16;" :: "r"(dst), "l"(src) : "memory");
}
__device__ __forceinline__ void load_tile_async(const __half* __restrict__ src, int ld,
                                                int row0, int k0, uint32_t dstb, int tid)
{
    #pragma unroll
    for (int i = 0; i < 2; i++) {
        int idx = i * 256 + tid;
        int rr = idx >> 2;
        int q  = idx & 3;
        cpa16(dstb + rr * (TSTRIDE*4) + q * 16,
              src + (size_t)(row0 + rr) * ld + k0 + q * 8);
    }
}
__device__ __forceinline__ void mma_fp16(float* c, const uint32_t* a, const uint32_t* b)
{
    asm volatile(
        "mma.sync.aligned.m16n8k16.row.col.f32.f16.f16.f32 "
        "{%0,%1,%2,%3}, {%4,%5,%6,%7}, {%8,%9}, {%0,%1,%2,%3};"
        : "+f"(c[0]), "+f"(c[1]), "+f"(c[2]), "+f"(c[3])
        : "r"(a[0]), "r"(a[1]), "r"(a[2]), "r"(a[3]), "r"(b[0]), "r"(b[1]));
}
__device__ __forceinline__ void ldmx4(uint32_t* r, uint32_t addr)
{
    asm volatile("ldmatrix.sync.aligned.m8n8.x4.shared.b16 {%0,%1,%2,%3}, [%4];"
        : "=r"(r[0]), "=r"(r[1]), "=r"(r[2]), "=r"(r[3]) : "r"(addr));
}

template<int AMODE, int EPI, bool RELU, int OMODE>
__global__ void __launch_bounds__(256, 2) gemm_mma(
    int AId, int WId,
    const float* __restrict__ biasPtr,
    int outId, int N, int K)
{
    extern __shared__ uint32_t sm[];
    const int tid  = threadIdx.x;
    const int wid  = tid >> 5;
    const int lane = tid & 31;
    const int wm   = wid >> 2;
    const int wn   = wid & 3;
    const int grp  = lane >> 2;
    const int tig  = lane & 3;
    const int bm   = blockIdx.y * 128;
    const int bn   = blockIdx.x * 128;

    const __half* Wh = hsel(WId);
    const __half* Ah = (AMODE == 0) ? hsel(AId) : nullptr;

    const uint32_t smb = smem_u32(sm);
    const int NCH = K >> 5;

    const int lrow = lane & 7;
    const int lsel = (lane >> 3) & 1;
    const int lhi  = lane >> 4;

    float acc[4][4][4];
    #pragma unroll
    for (int i = 0; i < 4; i++)
        #pragma unroll
        for (int j = 0; j < 4; j++)
            #pragma unroll
            for (int q = 0; q < 4; q++) acc[i][j][q] = 0.f;

    auto issue_chunk = [&](int c) {
        const int buf = c & 1;
        const __half* pA; int ka, lda;
        if (AMODE == 0) { pA = Ah; ka = c * 32; lda = K; }
        else {
            int kg = c * 32, seg = kg >> 9; ka = kg & 511; lda = 512;
            if      (seg == 0) pA = h_x;
            else if (seg == 1) pA = h_ao;
            else               pA = h_p;
        }
        uint32_t base = smb + buf * 2 * TILE_B;
        load_tile_async(pA, lda, bm, ka,   base,          tid);
        load_tile_async(Wh, K,   bn, c*32, base + TILE_B, tid);
        asm volatile("cp.async.commit_group;" ::: "memory");
    };

    issue_chunk(0);
    asm volatile("cp.async.wait_group 0;" ::: "memory");
    __syncthreads();

    for (int c = 0; c < NCH; c++) {
        const int buf = c & 1;
        if (c + 1 < NCH) issue_chunk(c + 1);

        const uint32_t tA = smb + (buf * 2 + 0) * TILE_B;
        const uint32_t tW = smb + (buf * 2 + 1) * TILE_B;

        #pragma unroll
        for (int ks = 0; ks < 2; ks++) {
            const uint32_t aoff = (uint32_t)((lrow + lsel * 8) * (TSTRIDE*4) + ks * 32 + lhi * 16);
            const uint32_t boff = (uint32_t)((lrow + lhi * 8) * (TSTRIDE*4) + ks * 32 + lsel * 16);

            uint32_t ah[4][4], wreg[2][4];
            #pragma unroll
            for (int mi = 0; mi < 4; mi++) {
                uint32_t ro = (uint32_t)((wm * 64 + mi * 16) * (TSTRIDE*4));
                ldmx4(ah[mi], tA + ro + aoff);
            }
            #pragma unroll
            for (int p = 0; p < 2; p++) {
                uint32_t no = (uint32_t)((wn * 32 + p * 16) * (TSTRIDE*4));
                ldmx4(wreg[p], tW + no + boff);
            }
            #pragma unroll
            for (int mi = 0; mi < 4; mi++)
                #pragma unroll
                for (int nj = 0; nj < 4; nj++) {
                    const uint32_t* bh = &wreg[nj >> 1][(nj & 1) * 2];
                    mma_fp16(acc[mi][nj], ah[mi], bh);
                }
        }
        asm volatile("cp.async.wait_group 0;" ::: "memory");
        __syncthreads();
    }

    float* Cf = (OMODE == 0) ? gsel(nullptr, outId) : nullptr;
    __half* Oh = (OMODE == 1) ? hsel(outId) : nullptr;

    #pragma unroll
    for (int mi = 0; mi < 4; mi++) {
        #pragma unroll
        for (int nj = 0; nj < 4; nj++) {
            int n = bn + wn * 32 + nj * 8 + tig * 2;
            #pragma unroll
            for (int half = 0; half < 2; half++) {
                int m = bm + wm * 64 + mi * 16 + grp + half * 8;
                float v0 = acc[mi][nj][half * 2 + 0];
                float v1 = acc[mi][nj][half * 2 + 1];
                float bv0, bv1;
                if (EPI == 0) { bv0 = biasPtr[n]; bv1 = biasPtr[n + 1]; }
                else { bv0 = g_ctxadd[(m >> 12) * DD + n]; bv1 = g_ctxadd[(m >> 12) * DD + n + 1]; }
                v0 += bv0; v1 += bv1;
                if (RELU) { v0 = fmaxf(v0, 0.f); v1 = fmaxf(v1, 0.f); }
                if (OMODE == 0) {
                    *reinterpret_cast<float2*>(&Cf[(size_t)m * N + n]) = make_float2(v0, v1);
                } else {
                    *reinterpret_cast<uint32_t*>(&Oh[(size_t)m * N + n]) =
                        pack2h(__float2half_rn(v0), __float2half_rn(v1));
                }
            }
        }
    }
}

// ---------------- launch ----------------------------------------------------
extern "C" void kernel_launch(void* const* d_in, const int* in_sizes, int n_in,
                              void* d_out, int out_size)
{
    const float* x          = (const float*)d_in[0];
    const float* context    = (const float*)d_in[1];
    const void*  pad_mask   = d_in[2];
    const float* film_ln_g  = (const float*)d_in[3];
    const float* film_ln_b  = (const float*)d_in[4];
    const float* film_w     = (const float*)d_in[5];
    const float* film_b     = (const float*)d_in[6];
    const float* concat_w   = (const float*)d_in[7];
    const float* concat_b   = (const float*)d_in[8];
    const float* concat_ln_g= (const float*)d_in[9];
    const float* concat_ln_b= (const float*)d_in[10];
    const float* ctx_w1     = (const float*)d_in[11];
    const float* ctx_b1     = (const float*)d_in[12];
    const float* ctx_w2     = (const float*)d_in[13];
    const float* ctx_b2     = (const float*)d_in[14];
    const float* q_ln_g     = (const float*)d_in[15];
    const float* q_ln_b     = (const float*)d_in[16];
    const float* in_proj_w  = (const float*)d_in[17];
    const float* in_proj_b  = (const float*)d_in[18];
    const float* out_proj_w = (const float*)d_in[19];
    const float* out_proj_b = (const float*)d_in[20];
    const float* mix_w1     = (const float*)d_in[21];
    const float* mix_b1     = (const float*)d_in[22];
    const float* mix_w2     = (const float*)d_in[23];
    const float* mix_b2     = (const float*)d_in[24];
    const float* out_ln_g   = (const float*)d_in[25];
    const float* out_ln_b   = (const float*)d_in[26];
    const float* gate_w     = (const float*)d_in[27];
    const float* gate_b     = (const float*)d_in[28];
    float* out = (float*)d_out;

    cudaFuncSetAttribute(gemm_mma<0,1,true, 1>, cudaFuncAttributeMaxDynamicSharedMemorySize, GM_SMEM);
    cudaFuncSetAttribute(gemm_mma<1,0,true, 1>, cudaFuncAttributeMaxDynamicSharedMemorySize, GM_SMEM);
    cudaFuncSetAttribute(gemm_mma<0,0,false,1>, cudaFuncAttributeMaxDynamicSharedMemorySize, GM_SMEM);

    detect_mask_kernel<<<1, 256>>>((const unsigned char*)pad_mask);

    // context-side fused front-end
    ctx_stage1<<<(20480+7)/8, 256>>>(context, film_w, film_b, gate_w, gate_b,
                                     ctx_w1, ctx_b1, concat_w, concat_b);
    small_gemmW<<<(BB*TT*DD+7)/8, 256>>>(nullptr, 3, HC, ctx_w2, HC, ctx_b2, 5, BB, 1024, HC, 0);
    kv_mvo_kernel<<<16, 512>>>(in_proj_w, in_proj_b, out_proj_w, in_proj_b);

    // fused weight prep
    prep_weights<<<(PW_TOT+255)/256, 256>>>(concat_w, mix_w2, mix_w1);

    // fused LN + attention + mix prep
    ln_base_attn_kernel<<<BL, 128>>>(x, q_ln_g, q_ln_b, out_proj_b);

    // updc = relu(x @ wc^T + ctxadd[b])  -> fp16 (concat-LN folded into final)
    gemm_mma<0,1,true,1><<<dim3(4, 256), 256, GM_SMEM>>>(1, 15, nullptr, 18, DD, DD);

    // mixh = relu([x|ao|x*ao] @ W1c^T + b1), fp16 output
    gemm_mma<1,0,true,1><<<dim3(8, 256), 256, GM_SMEM>>>(0, 16, mix_b1, 11, H2, 1536);

    // upda = mixh @ w2^T + b2 -> fp16
    gemm_mma<0,0,false,1><<<dim3(4, 256), 256, GM_SMEM>>>(11, 17, mix_b2, 19, DD, H2);

    // final: recompute film base from x, inline concat-LN, gate, out-LN
    final_kernel<<<BL, 128>>>(x, pad_mask, film_ln_g, film_ln_b,
                              concat_ln_g, concat_ln_b, out_ln_g, out_ln_b, out);

    (void)in_sizes; (void)n_in; (void)out_size;
}

// round 16
// speedup vs baseline: 2.3616x; 2.3616x over previous
#include <cuda_runtime.h>
#include <cuda_bf16.h>
#include <cuda_fp16.h>
#include <math.h>
#include <stdint.h>

#define BB   8
#define LL   4096
#define BL   (BB*LL)
#define DD   512
#define CC   256
#define TT   2
#define HC   512
#define H2   1024
#define LN_EPS 1e-5f

// ---------------- fp32 scratch (ids for gsel; never passed from host) ------
__device__ float g_gb[BB*1024];          // 1
__device__ float g_gate[BB*DD];          // 2
__device__ float g_h[BB*HC];             // 3
__device__ float g_ctxadd[BB*DD];        // 4
__device__ float g_ctxtok[BB*TT*DD];     // 5
__device__ float g_k[BB*TT*DD];          // 6
__device__ float g_v[BB*TT*DD];          // 7
__device__ float g_m[32*DD];             // attention score vectors (b,t,h)
__device__ float g_vo[32*DD];            // out-projected v vectors (b,t,h)
__device__ float g_sb[32];               // per-(b,t,h) score bias
__device__ int   g_maskmode;

// ---------------- fp16 scratch (ids for hsel) -------------------------------
__device__ __half h_x   [(size_t)BL*DD];  // 1
__device__ __half h_ao  [(size_t)BL*DD];  // 7
__device__ __half h_p   [(size_t)BL*DD];  // 9
__device__ __half h_mh  [(size_t)BL*H2];  // 11
__device__ __half h_wc[DD*DD];            // 15
__device__ __half h_w1[H2*1536];          // 16
__device__ __half h_w2[DD*H2];            // 17
__device__ __half h_updc[(size_t)BL*DD];  // 18
__device__ __half h_upda[(size_t)BL*DD];  // 19

__device__ __forceinline__ float* gsel(const float* p, int id)
{
    switch (id) {
        case 1: return g_gb;     case 2: return g_gate;   case 3: return g_h;
        case 4: return g_ctxadd; case 5: return g_ctxtok; case 6: return g_k;
        case 7: return g_v;
        default: return const_cast<float*>(p);
    }
}
__device__ __forceinline__ __half* hsel(int id)
{
    switch (id) {
        case 1: return h_x;    case 7: return h_ao;   case 9: return h_p;
        case 11: return h_mh;  case 15: return h_wc;  case 16: return h_w1;
        case 17: return h_w2;  case 18: return h_updc;case 19: return h_upda;
        default: return nullptr;
    }
}

__device__ __forceinline__ uint32_t pack2h(__half a, __half b)
{
    return (uint32_t)__half_as_ushort(a) | ((uint32_t)__half_as_ushort(b) << 16);
}
__device__ __forceinline__ uint32_t smem_u32(const void* p)
{
    uint32_t a;
    asm("{ .reg .u64 t; cvta.to.shared.u64 t, %1; cvt.u32.u64 %0, t; }" : "=r"(a) : "l"(p));
    return a;
}
__device__ __forceinline__ void unpack2h(uint32_t w, float& a, float& b)
{
    a = __half2float(__ushort_as_half((unsigned short)(w & 0xffff)));
    b = __half2float(__ushort_as_half((unsigned short)(w >> 16)));
}

// ---------------- mask dtype detection -------------------------------------
__global__ void detect_mask_kernel(const unsigned char* __restrict__ m)
{
    __shared__ int s_gt1, s_odd;
    if (threadIdx.x == 0) { s_gt1 = 0; s_odd = 0; }
    __syncthreads();
    int lgt1 = 0, lodd = 0;
    for (int i = threadIdx.x; i < BL; i += 256) {
        unsigned char v = m[i];
        if (v > 1) lgt1 = 1;
        if ((i & 3) && v) lodd = 1;
    }
    if (lgt1) atomicOr(&s_gt1, 1);
    if (lodd) atomicOr(&s_odd, 1);
    __syncthreads();
    if (threadIdx.x == 0) g_maskmode = (!s_gt1 && s_odd) ? 1 : 0;
}

// ---------------- fused context stage-1 (warp per output, 4 sub-GEMMs) ------
__global__ void ctx_stage1(const float* __restrict__ context,
                           const float* __restrict__ film_w, const float* __restrict__ film_b,
                           const float* __restrict__ gate_w, const float* __restrict__ gate_b,
                           const float* __restrict__ ctx_w1, const float* __restrict__ ctx_b1,
                           const float* __restrict__ concat_w, const float* __restrict__ concat_b)
{
    int o = blockIdx.x * 8 + (threadIdx.x >> 5);
    if (o >= 20480) return;
    int lane = threadIdx.x & 31;
    int m, n, act; const float* w; const float* bias; float* outp; int oidx;
    if (o < 8192)       { int oo = o;         m = oo >> 10; n = oo & 1023; w = film_w + (size_t)n*CC; bias = film_b; act = 0; outp = g_gb;     oidx = oo; }
    else if (o < 12288) { int oo = o - 8192;  m = oo >> 9;  n = oo & 511;  w = gate_w + (size_t)n*CC; bias = gate_b; act = 2; outp = g_gate;   oidx = oo; }
    else if (o < 16384) { int oo = o - 12288; m = oo >> 9;  n = oo & 511;  w = ctx_w1 + (size_t)n*CC; bias = ctx_b1; act = 1; outp = g_h;      oidx = oo; }
    else                { int oo = o - 16384; m = oo >> 9;  n = oo & 511;  w = concat_w + (size_t)n*(DD+CC) + DD; bias = concat_b; act = 0; outp = g_ctxadd; oidx = oo; }
    const float* a = context + (size_t)m * CC;
    float s = 0.f;
    for (int k = lane; k < CC; k += 32) s += a[k] * w[k];
    #pragma unroll
    for (int off = 16; off; off >>= 1) s += __shfl_down_sync(0xffffffffu, s, off);
    if (lane == 0) {
        s += bias[n];
        if (act == 1)      s = 0.5f * s * (1.f + erff(s * 0.70710678118654752f));
        else if (act == 2) s = 1.f / (1.f + expf(-s));
        outp[oidx] = s;
    }
}

// ---------------- generic small GEMM (warp per output) ----------------------
__global__ void small_gemmW(const float* __restrict__ Ap, int Aid, int lda,
                            const float* __restrict__ W, int ldw,
                            const float* __restrict__ bias,
                            int outid, int M, int N, int K, int act)
{
    const float* A = gsel(Ap, Aid);
    float* out = gsel(nullptr, outid);
    int o = blockIdx.x * 8 + (threadIdx.x >> 5);
    if (o >= M * N) return;
    int lane = threadIdx.x & 31;
    int m = o / N, n = o % N;
    const float* a = A + (size_t)m * lda;
    const float* w = W + (size_t)n * ldw;
    float s = 0.f;
    for (int k = lane; k < K; k += 32) s += a[k] * w[k];
    #pragma unroll
    for (int off = 16; off; off >>= 1) s += __shfl_down_sync(0xffffffffu, s, off);
    if (lane == 0) {
        s += bias[n];
        if (act == 1)      s = 0.5f * s * (1.f + erff(s * 0.70710678118654752f));
        else if (act == 2) s = 1.f / (1.f + expf(-s));
        out[o] = s;
    }
}

// ---------------- attention precompute (round-14 proven versions) -----------
// idx = b*4 + t*2 + h. m[idx][d] = sum_j wq[h*256+j][d] * k[b,t,h*256+j]
__global__ void m_kernel(const float* __restrict__ wq, const float* __restrict__ bq)
{
    int idx = blockIdx.x;
    int h = idx & 1, t = (idx >> 1) & 1, b = idx >> 2;
    __shared__ float sk[256];
    __shared__ float sred[16];
    int tid = threadIdx.x;   // 512
    if (tid < 256) sk[tid] = g_k[(b*2 + t)*512 + h*256 + tid];
    __syncthreads();
    const float* wcol = wq + (size_t)(h*256) * 512 + tid;
    float s = 0.f;
    #pragma unroll 4
    for (int j = 0; j < 256; j++) s += wcol[(size_t)j * 512] * sk[j];
    g_m[idx*512 + tid] = s;
    float pb = (tid < 256) ? bq[h*256 + tid] * sk[tid] : 0.f;
    #pragma unroll
    for (int off = 16; off; off >>= 1) pb += __shfl_down_sync(0xffffffffu, pb, off);
    if ((tid & 31) == 0) sred[tid >> 5] = pb;
    __syncthreads();
    if (tid == 0) {
        float tot = 0.f;
        #pragma unroll
        for (int i = 0; i < 16; i++) tot += sred[i];
        g_sb[idx] = tot;
    }
}

// vo[idx][d] = sum_j wo[d][h*256+j] * v[b,t,h*256+j]   (warp per output)
__global__ void vo_kernel(const float* __restrict__ wo)
{
    int o = blockIdx.x * 8 + (threadIdx.x >> 5);
    if (o >= 32*512) return;
    int lane = threadIdx.x & 31;
    int d = o & 511, idx = o >> 9;
    int h = idx & 1, t = (idx >> 1) & 1, b = idx >> 2;
    const float* wrow = wo + (size_t)d * 512 + h*256;
    const float* vv = g_v + (b*2 + t)*512 + h*256;
    float s = 0.f;
    #pragma unroll
    for (int j = lane; j < 256; j += 32) s += wrow[j] * vv[j];
    #pragma unroll
    for (int off = 16; off; off >>= 1) s += __shfl_down_sync(0xffffffffu, s, off);
    if (lane == 0) g_vo[o] = s;
}

// ---------------- fused weight prep (wc, w2, w1c -> fp16) -------------------
#define PW_WC  (DD*DD)
#define PW_W2  (DD*H2)
#define PW_TOT (PW_WC + PW_W2 + H2*1536)
__global__ void prep_weights(const float* __restrict__ concat_w,
                             const float* __restrict__ mix_w2,
                             const float* __restrict__ mw1)
{
    int i = blockIdx.x * blockDim.x + threadIdx.x;
    if (i >= PW_TOT) return;
    if (i < PW_WC) {
        int n = i >> 9, k = i & 511;
        h_wc[i] = __float2half_rn(concat_w[(size_t)n * (DD+CC) + k]);
    } else if (i < PW_WC + PW_W2) {
        int j = i - PW_WC;
        h_w2[j] = __float2half_rn(mix_w2[j]);
    } else {
        int j = i - PW_WC - PW_W2;
        int n = j / 1536, k = j % 1536;
        const float* r = mw1 + (size_t)n * 2048;
        float v;
        if      (k < 512)  v = r[k] + r[k + 1024];
        else if (k < 1024) v = r[k] - r[k + 512];
        else               v = r[k + 512];
        h_w1[j] = __float2half_rn(v);
    }
}

// ---------------- block reduce ----------------------------------------------
__device__ __forceinline__ float2 block_reduce2_128(float a, float b)
{
    __shared__ float sa[4], sb[4];
    __syncthreads();
    int lane = threadIdx.x & 31, w = threadIdx.x >> 5;
    #pragma unroll
    for (int o = 16; o; o >>= 1) {
        a += __shfl_down_sync(0xffffffffu, a, o);
        b += __shfl_down_sync(0xffffffffu, b, o);
    }
    if (lane == 0) { sa[w] = a; sb[w] = b; }
    __syncthreads();
    return make_float2(sa[0]+sa[1]+sa[2]+sa[3], sb[0]+sb[1]+sb[2]+sb[3]);
}

// ---------------- fused LN + attention + mix prep (vectorized) --------------
__global__ void ln_base_attn_kernel(const float* __restrict__ x,
                                    const float* __restrict__ qg, const float* __restrict__ qb,
                                    const float* __restrict__ bo)
{
    int row = blockIdx.x;
    int b = row >> 12;
    int tid = threadIdx.x;
    int d0 = tid * 4;
    const float4 xv = *reinterpret_cast<const float4*>(x + (size_t)row * DD + d0);
    float v[4] = {xv.x, xv.y, xv.z, xv.w};
    float s = v[0]+v[1]+v[2]+v[3];
    float s2 = v[0]*v[0]+v[1]*v[1]+v[2]*v[2]+v[3]*v[3];
    float2 r = block_reduce2_128(s, s2);
    float mean = r.x * (1.f / DD);
    float inv  = rsqrtf(r.y * (1.f / DD) - mean * mean + LN_EPS);

    size_t vecidx = (size_t)row * 128 + tid;
    reinterpret_cast<uint2*>(h_x)[vecidx] = make_uint2(
        pack2h(__float2half_rn(v[0]), __float2half_rn(v[1])),
        pack2h(__float2half_rn(v[2]), __float2half_rn(v[3])));

    float4 qgv = *reinterpret_cast<const float4*>(qg + d0);
    float4 qbv = *reinterpret_cast<const float4*>(qb + d0);
    float xq[4];
    xq[0] = (v[0]-mean)*inv*qgv.x + qbv.x;
    xq[1] = (v[1]-mean)*inv*qgv.y + qbv.y;
    xq[2] = (v[2]-mean)*inv*qgv.z + qbv.z;
    xq[3] = (v[3]-mean)*inv*qgv.w + qbv.w;

    float sc[4];
    #pragma unroll
    for (int j = 0; j < 4; j++) {
        float4 mv = *reinterpret_cast<const float4*>(g_m + (size_t)(b*4 + j)*512 + d0);
        sc[j] = xq[0]*mv.x + xq[1]*mv.y + xq[2]*mv.z + xq[3]*mv.w;
    }
    __shared__ float red[4][4];
    int lane = tid & 31, w = tid >> 5;
    #pragma unroll
    for (int o = 16; o; o >>= 1) {
        sc[0] += __shfl_down_sync(0xffffffffu, sc[0], o);
        sc[1] += __shfl_down_sync(0xffffffffu, sc[1], o);
        sc[2] += __shfl_down_sync(0xffffffffu, sc[2], o);
        sc[3] += __shfl_down_sync(0xffffffffu, sc[3], o);
    }
    __syncthreads();
    if (lane == 0) { red[w][0]=sc[0]; red[w][1]=sc[1]; red[w][2]=sc[2]; red[w][3]=sc[3]; }
    __syncthreads();
    float s00 = (red[0][0]+red[1][0]+red[2][0]+red[3][0] + g_sb[b*4+0]) * 0.0625f; // t0 h0
    float s01 = (red[0][1]+red[1][1]+red[2][1]+red[3][1] + g_sb[b*4+1]) * 0.0625f; // t0 h1
    float s10 = (red[0][2]+red[1][2]+red[2][2]+red[3][2] + g_sb[b*4+2]) * 0.0625f; // t1 h0
    float s11 = (red[0][3]+red[1][3]+red[2][3]+red[3][3] + g_sb[b*4+3]) * 0.0625f; // t1 h1

    float m0 = fmaxf(s00, s10), m1 = fmaxf(s01, s11);
    float e00 = expf(s00 - m0), e10 = expf(s10 - m0);
    float e01 = expf(s01 - m1), e11 = expf(s11 - m1);
    float p00 = e00/(e00+e10), p01 = e10/(e00+e10);
    float p10 = e01/(e01+e11), p11 = e11/(e01+e11);

    float4 vo0 = *reinterpret_cast<const float4*>(g_vo + (size_t)(b*4 + 0)*512 + d0);
    float4 vo1 = *reinterpret_cast<const float4*>(g_vo + (size_t)(b*4 + 1)*512 + d0);
    float4 vo2 = *reinterpret_cast<const float4*>(g_vo + (size_t)(b*4 + 2)*512 + d0);
    float4 vo3 = *reinterpret_cast<const float4*>(g_vo + (size_t)(b*4 + 3)*512 + d0);
    float4 bov = *reinterpret_cast<const float4*>(bo + d0);
    float ao[4];
    ao[0] = p00*vo0.x + p10*vo1.x + p01*vo2.x + p11*vo3.x + bov.x;
    ao[1] = p00*vo0.y + p10*vo1.y + p01*vo2.y + p11*vo3.y + bov.y;
    ao[2] = p00*vo0.z + p10*vo1.z + p01*vo2.z + p11*vo3.z + bov.z;
    ao[3] = p00*vo0.w + p10*vo1.w + p01*vo2.w + p11*vo3.w + bov.w;

    reinterpret_cast<uint2*>(h_ao)[vecidx] = make_uint2(
        pack2h(__float2half_rn(ao[0]), __float2half_rn(ao[1])),
        pack2h(__float2half_rn(ao[2]), __float2half_rn(ao[3])));
    reinterpret_cast<uint2*>(h_p)[vecidx] = make_uint2(
        pack2h(__float2half_rn(v[0]*ao[0]), __float2half_rn(v[1]*ao[1])),
        pack2h(__float2half_rn(v[2]*ao[2]), __float2half_rn(v[3]*ao[3])));
}

// ---------------- final: recompute film base, concat-LN inline, out-LN ------
__global__ void final_kernel(const float* __restrict__ x,
                             const void* __restrict__ mask,
                             const float* __restrict__ fg, const float* __restrict__ fb,
                             const float* __restrict__ cg, const float* __restrict__ cb,
                             const float* __restrict__ og, const float* __restrict__ ob,
                             float* __restrict__ out)
{
    int row = blockIdx.x;
    int b = row >> 12;
    int tid = threadIdx.x;
    int d0 = tid * 4;
    float mk = (g_maskmode == 1) ? (((const unsigned char*)mask)[row] ? 1.f : 0.f)
                                 : ((((const int*)mask)[row] != 0) ? 1.f : 0.f);
    size_t vecidx = (size_t)row * 128 + tid;

    const float4 xv = *reinterpret_cast<const float4*>(x + (size_t)row * DD + d0);
    float v[4] = {xv.x, xv.y, xv.z, xv.w};
    float2 xr = block_reduce2_128(v[0]+v[1]+v[2]+v[3],
                                  v[0]*v[0]+v[1]*v[1]+v[2]*v[2]+v[3]*v[3]);
    float xmean = xr.x * (1.f / DD);
    float xinv  = rsqrtf(xr.y * (1.f / DD) - xmean * xmean + LN_EPS);

    uint2 uw = reinterpret_cast<const uint2*>(h_updc)[vecidx];
    float u[4];
    unpack2h(uw.x, u[0], u[1]);
    unpack2h(uw.y, u[2], u[3]);
    float2 ur = block_reduce2_128(u[0]+u[1]+u[2]+u[3],
                                  u[0]*u[0]+u[1]*u[1]+u[2]*u[2]+u[3]*u[3]);
    float umean = ur.x * (1.f / DD);
    float uinv  = rsqrtf(ur.y * (1.f / DD) - umean * umean + LN_EPS);

    uint2 aw = reinterpret_cast<const uint2*>(h_upda)[vecidx];
    float ua[4];
    unpack2h(aw.x, ua[0], ua[1]);
    unpack2h(aw.y, ua[2], ua[3]);

    float4 fgv = *reinterpret_cast<const float4*>(fg + d0);
    float4 fbv = *reinterpret_cast<const float4*>(fb + d0);
    float4 gav = *reinterpret_cast<const float4*>(g_gb + b*1024 + d0);
    float4 bev = *reinterpret_cast<const float4*>(g_gb + b*1024 + 512 + d0);
    float4 cgv = *reinterpret_cast<const float4*>(cg + d0);
    float4 cbv = *reinterpret_cast<const float4*>(cb + d0);
    float4 gtv = *reinterpret_cast<const float4*>(g_gate + b*DD + d0);

    float fgA[4] = {fgv.x,fgv.y,fgv.z,fgv.w}, fbA[4] = {fbv.x,fbv.y,fbv.z,fbv.w};
    float gaA[4] = {gav.x,gav.y,gav.z,gav.w}, beA[4] = {bev.x,bev.y,bev.z,bev.w};
    float cgA[4] = {cgv.x,cgv.y,cgv.z,cgv.w}, cbA[4] = {cbv.x,cbv.y,cbv.z,cbv.w};
    float gtA[4] = {gtv.x,gtv.y,gtv.z,gtv.w};

    float val[4], vs = 0.f, vs2 = 0.f;
    #pragma unroll
    for (int i = 0; i < 4; i++) {
        float xh = (v[i] - xmean) * xinv;
        float base = (1.f + gaA[i]) * (xh * fgA[i] + fbA[i]) + beA[i];
        float uln  = (u[i] - umean) * uinv * cgA[i] + cbA[i];
        val[i] = base + gtA[i] * mk * (uln + ua[i]);
        vs += val[i]; vs2 += val[i] * val[i];
    }
    float2 rr = block_reduce2_128(vs, vs2);
    float mean = rr.x * (1.f / DD);
    float inv  = rsqrtf(rr.y * (1.f / DD) - mean * mean + LN_EPS);
    float4 ogv = *reinterpret_cast<const float4*>(og + d0);
    float4 obv = *reinterpret_cast<const float4*>(ob + d0);
    float4 o;
    o.x = (val[0] - mean) * inv * ogv.x + obv.x;
    o.y = (val[1] - mean) * inv * ogv.y + obv.y;
    o.z = (val[2] - mean) * inv * ogv.z + obv.z;
    o.w = (val[3] - mean) * inv * ogv.w + obv.w;
    *reinterpret_cast<float4*>(out + (size_t)row * DD + d0) = o;
}

// ---------------- mma.sync single-pass fp16 GEMM (ldmatrix fragments) --------
#define TSTRIDE 20
#define TILE_U32 (128*TSTRIDE)
#define TILE_B   (TILE_U32*4)
#define GM_SMEM  (4*TILE_B)

__device__ __forceinline__ void cpa16(uint32_t dst, const void* src)
{
    asm volatile("cp.async.cg.shared.global [%0], [%1], 16;" :: "r"(dst), "l"(src) : "memory");
}
__device__ __forceinline__ void load_tile_async(const __half* __restrict__ src, int ld,
                                                int row0, int k0, uint32_t dstb, int tid)
{
    #pragma unroll
    for (int i = 0; i < 2; i++) {
        int idx = i * 256 + tid;
        int rr = idx >> 2;
        int q  = idx & 3;
        cpa16(dstb + rr * (TSTRIDE*4) + q * 16,
              src + (size_t)(row0 + rr) * ld + k0 + q * 8);
    }
}
__device__ __forceinline__ void mma_fp16(float* c, const uint32_t* a, const uint32_t* b)
{
    asm volatile(
        "mma.sync.aligned.m16n8k16.row.col.f32.f16.f16.f32 "
        "{%0,%1,%2,%3}, {%4,%5,%6,%7}, {%8,%9}, {%0,%1,%2,%3};"
        : "+f"(c[0]), "+f"(c[1]), "+f"(c[2]), "+f"(c[3])
        : "r"(a[0]), "r"(a[1]), "r"(a[2]), "r"(a[3]), "r"(b[0]), "r"(b[1]));
}
__device__ __forceinline__ void ldmx4(uint32_t* r, uint32_t addr)
{
    asm volatile("ldmatrix.sync.aligned.m8n8.x4.shared.b16 {%0,%1,%2,%3}, [%4];"
        : "=r"(r[0]), "=r"(r[1]), "=r"(r[2]), "=r"(r[3]) : "r"(addr));
}

template<int AMODE, int EPI, bool RELU, int OMODE>
__global__ void __launch_bounds__(256, 2) gemm_mma(
    int AId, int WId,
    const float* __restrict__ biasPtr,
    int outId, int N, int K)
{
    extern __shared__ uint32_t sm[];
    const int tid  = threadIdx.x;
    const int wid  = tid >> 5;
    const int lane = tid & 31;
    const int wm   = wid >> 2;
    const int wn   = wid & 3;
    const int grp  = lane >> 2;
    const int tig  = lane & 3;
    const int bm   = blockIdx.y * 128;
    const int bn   = blockIdx.x * 128;

    const __half* Wh = hsel(WId);
    const __half* Ah = (AMODE == 0) ? hsel(AId) : nullptr;

    const uint32_t smb = smem_u32(sm);
    const int NCH = K >> 5;

    const int lrow = lane & 7;
    const int lsel = (lane >> 3) & 1;
    const int lhi  = lane >> 4;

    float acc[4][4][4];
    #pragma unroll
    for (int i = 0; i < 4; i++)
        #pragma unroll
        for (int j = 0; j < 4; j++)
            #pragma unroll
            for (int q = 0; q < 4; q++) acc[i][j][q] = 0.f;

    auto issue_chunk = [&](int c) {
        const int buf = c & 1;
        const __half* pA; int ka, lda;
        if (AMODE == 0) { pA = Ah; ka = c * 32; lda = K; }
        else {
            int kg = c * 32, seg = kg >> 9; ka = kg & 511; lda = 512;
            if      (seg == 0) pA = h_x;
            else if (seg == 1) pA = h_ao;
            else               pA = h_p;
        }
        uint32_t base = smb + buf * 2 * TILE_B;
        load_tile_async(pA, lda, bm, ka,   base,          tid);
        load_tile_async(Wh, K,   bn, c*32, base + TILE_B, tid);
        asm volatile("cp.async.commit_group;" ::: "memory");
    };

    issue_chunk(0);
    asm volatile("cp.async.wait_group 0;" ::: "memory");
    __syncthreads();

    for (int c = 0; c < NCH; c++) {
        const int buf = c & 1;
        if (c + 1 < NCH) issue_chunk(c + 1);

        const uint32_t tA = smb + (buf * 2 + 0) * TILE_B;
        const uint32_t tW = smb + (buf * 2 + 1) * TILE_B;

        #pragma unroll
        for (int ks = 0; ks < 2; ks++) {
            const uint32_t aoff = (uint32_t)((lrow + lsel * 8) * (TSTRIDE*4) + ks * 32 + lhi * 16);
            const uint32_t boff = (uint32_t)((lrow + lhi * 8) * (TSTRIDE*4) + ks * 32 + lsel * 16);

            uint32_t ah[4][4], wreg[2][4];
            #pragma unroll
            for (int mi = 0; mi < 4; mi++) {
                uint32_t ro = (uint32_t)((wm * 64 + mi * 16) * (TSTRIDE*4));
                ldmx4(ah[mi], tA + ro + aoff);
            }
            #pragma unroll
            for (int p = 0; p < 2; p++) {
                uint32_t no = (uint32_t)((wn * 32 + p * 16) * (TSTRIDE*4));
                ldmx4(wreg[p], tW + no + boff);
            }
            #pragma unroll
            for (int mi = 0; mi < 4; mi++)
                #pragma unroll
                for (int nj = 0; nj < 4; nj++) {
                    const uint32_t* bh = &wreg[nj >> 1][(nj & 1) * 2];
                    mma_fp16(acc[mi][nj], ah[mi], bh);
                }
        }
        asm volatile("cp.async.wait_group 0;" ::: "memory");
        __syncthreads();
    }

    float* Cf = (OMODE == 0) ? gsel(nullptr, outId) : nullptr;
    __half* Oh = (OMODE == 1) ? hsel(outId) : nullptr;

    #pragma unroll
    for (int mi = 0; mi < 4; mi++) {
        #pragma unroll
        for (int nj = 0; nj < 4; nj++) {
            int n = bn + wn * 32 + nj * 8 + tig * 2;
            #pragma unroll
            for (int half = 0; half < 2; half++) {
                int m = bm + wm * 64 + mi * 16 + grp + half * 8;
                float v0 = acc[mi][nj][half * 2 + 0];
                float v1 = acc[mi][nj][half * 2 + 1];
                float bv0, bv1;
                if (EPI == 0) { bv0 = biasPtr[n]; bv1 = biasPtr[n + 1]; }
                else { bv0 = g_ctxadd[(m >> 12) * DD + n]; bv1 = g_ctxadd[(m >> 12) * DD + n + 1]; }
                v0 += bv0; v1 += bv1;
                if (RELU) { v0 = fmaxf(v0, 0.f); v1 = fmaxf(v1, 0.f); }
                if (OMODE == 0) {
                    *reinterpret_cast<float2*>(&Cf[(size_t)m * N + n]) = make_float2(v0, v1);
                } else {
                    *reinterpret_cast<uint32_t*>(&Oh[(size_t)m * N + n]) =
                        pack2h(__float2half_rn(v0), __float2half_rn(v1));
                }
            }
        }
    }
}

// ---------------- launch ----------------------------------------------------
extern "C" void kernel_launch(void* const* d_in, const int* in_sizes, int n_in,
                              void* d_out, int out_size)
{
    const float* x          = (const float*)d_in[0];
    const float* context    = (const float*)d_in[1];
    const void*  pad_mask   = d_in[2];
    const float* film_ln_g  = (const float*)d_in[3];
    const float* film_ln_b  = (const float*)d_in[4];
    const float* film_w     = (const float*)d_in[5];
    const float* film_b     = (const float*)d_in[6];
    const float* concat_w   = (const float*)d_in[7];
    const float* concat_b   = (const float*)d_in[8];
    const float* concat_ln_g= (const float*)d_in[9];
    const float* concat_ln_b= (const float*)d_in[10];
    const float* ctx_w1     = (const float*)d_in[11];
    const float* ctx_b1     = (const float*)d_in[12];
    const float* ctx_w2     = (const float*)d_in[13];
    const float* ctx_b2     = (const float*)d_in[14];
    const float* q_ln_g     = (const float*)d_in[15];
    const float* q_ln_b     = (const float*)d_in[16];
    const float* in_proj_w  = (const float*)d_in[17];
    const float* in_proj_b  = (const float*)d_in[18];
    const float* out_proj_w = (const float*)d_in[19];
    const float* out_proj_b = (const float*)d_in[20];
    const float* mix_w1     = (const float*)d_in[21];
    const float* mix_b1     = (const float*)d_in[22];
    const float* mix_w2     = (const float*)d_in[23];
    const float* mix_b2     = (const float*)d_in[24];
    const float* out_ln_g   = (const float*)d_in[25];
    const float* out_ln_b   = (const float*)d_in[26];
    const float* gate_w     = (const float*)d_in[27];
    const float* gate_b     = (const float*)d_in[28];
    float* out = (float*)d_out;

    cudaFuncSetAttribute(gemm_mma<0,1,true, 1>, cudaFuncAttributeMaxDynamicSharedMemorySize, GM_SMEM);
    cudaFuncSetAttribute(gemm_mma<1,0,true, 1>, cudaFuncAttributeMaxDynamicSharedMemorySize, GM_SMEM);
    cudaFuncSetAttribute(gemm_mma<0,0,false,1>, cudaFuncAttributeMaxDynamicSharedMemorySize, GM_SMEM);

    detect_mask_kernel<<<1, 256>>>((const unsigned char*)pad_mask);

    // context-side front-end (all warp-per-output, coalesced)
    ctx_stage1<<<(20480+7)/8, 256>>>(context, film_w, film_b, gate_w, gate_b,
                                     ctx_w1, ctx_b1, concat_w, concat_b);
    small_gemmW<<<(BB*1024+7)/8, 256>>>(nullptr, 3, HC, ctx_w2, HC, ctx_b2, 5, BB, 1024, HC, 0);
    small_gemmW<<<(BB*TT*DD+7)/8, 256>>>(nullptr, 5, DD, in_proj_w + (size_t)DD*DD,   DD, in_proj_b + DD,   6, BB*TT, DD, DD, 0);
    small_gemmW<<<(BB*TT*DD+7)/8, 256>>>(nullptr, 5, DD, in_proj_w + (size_t)2*DD*DD, DD, in_proj_b + 2*DD, 7, BB*TT, DD, DD, 0);
    m_kernel<<<32, 512>>>(in_proj_w, in_proj_b);
    vo_kernel<<<(32*512+7)/8, 256>>>(out_proj_w);

    // fused weight prep
    prep_weights<<<(PW_TOT+255)/256, 256>>>(concat_w, mix_w2, mix_w1);

    // fused LN + attention + mix prep
    ln_base_attn_kernel<<<BL, 128>>>(x, q_ln_g, q_ln_b, out_proj_b);

    // updc = relu(x @ wc^T + ctxadd[b]) -> fp16 (concat-LN folded into final)
    gemm_mma<0,1,true,1><<<dim3(4, 256), 256, GM_SMEM>>>(1, 15, nullptr, 18, DD, DD);

    // mixh = relu([x|ao|x*ao] @ W1c^T + b1), fp16 output
    gemm_mma<1,0,true,1><<<dim3(8, 256), 256, GM_SMEM>>>(0, 16, mix_b1, 11, H2, 1536);

    // upda = mixh @ w2^T + b2 -> fp16
    gemm_mma<0,0,false,1><<<dim3(4, 256), 256, GM_SMEM>>>(11, 17, mix_b2, 19, DD, H2);

    // final: recompute film base from x, inline concat-LN, gate, out-LN
    final_kernel<<<BL, 128>>>(x, pad_mask, film_ln_g, film_ln_b,
                              concat_ln_g, concat_ln_b, out_ln_g, out_ln_b, out);

    (void)in_sizes; (void)n_in; (void)out_size;
}